// round 7
// baseline (speedup 1.0000x reference)
#include <cuda_runtime.h>
#include <cuda_fp16.h>

#define NN 50000
#define NE 1600000
#define NEG 0.2f
#define W 128           // ELL width (in-degree is Poisson(32); max ~65)
#define NOVF 65536      // overflow insurance capacity

// ---------------- scratch (device globals; no allocation allowed) ----------
__device__ float4 g_hq[NN];          // per-node h_q (4 heads)
__device__ float4 g_kact[NN];        // per-node leaky(x@Wk^T)
__device__ float4 g_qagg[NN];        // per-node aggregated q
__device__ __half g_hproj[NN * 128]; // per-node x@Wl^T + bl (fp16 storage, fp32 compute)
__device__ int    g_deg[NN];
__device__ int    g_ell[NN * W];     // ELL adjacency: cols of incoming edges
__device__ int    g_ovf_r[NOVF];
__device__ int    g_ovf_c[NOVF];
__device__ int    g_novf;

// ---------------- init ----------------
__global__ void kzero() {
    int i = blockIdx.x * blockDim.x + threadIdx.x;
    if (i < NN) g_deg[i] = 0;
    if (i == 0) g_novf = 0;
}

// ---------------- single-pass ELL build, 4 edges/thread for MLP ------------
__global__ void kbuild(const int* __restrict__ ei) {
    int t = blockIdx.x * blockDim.x + threadIdx.x;
    int e0 = t * 4;
    if (e0 >= NE) return;
    int4 r4 = *(const int4*)&ei[e0];
    int4 c4 = *(const int4*)&ei[NE + e0];
    int rr[4] = {r4.x, r4.y, r4.z, r4.w};
    int cc[4] = {c4.x, c4.y, c4.z, c4.w};
    int pp[4];
#pragma unroll
    for (int j = 0; j < 4; j++) pp[j] = atomicAdd(&g_deg[rr[j]], 1);
#pragma unroll
    for (int j = 0; j < 4; j++) {
        if (pp[j] < W) {
            g_ell[rr[j] * W + pp[j]] = cc[j];
        } else {
            int o = atomicAdd(&g_novf, 1);
            if (o < NOVF) { g_ovf_r[o] = rr[j]; g_ovf_c[o] = cc[j]; }
        }
    }
}

// ---------------- per-node small projections: h_q, k_act -------------------
__global__ void kprojsmall(const float* __restrict__ x,
                           const float* __restrict__ Wq,
                           const float* __restrict__ Wk) {
    int w = (blockIdx.x * blockDim.x + threadIdx.x) >> 5;
    int lane = threadIdx.x & 31;
    if (w >= NN) return;
    float4 xv = ((const float4*)x)[w * 32 + lane];
    float a[8];
#pragma unroll
    for (int h = 0; h < 4; h++) {
        float4 q = ((const float4*)Wq)[h * 32 + lane];
        float4 k = ((const float4*)Wk)[h * 32 + lane];
        a[h]     = xv.x * q.x + xv.y * q.y + xv.z * q.z + xv.w * q.w;
        a[4 + h] = xv.x * k.x + xv.y * k.y + xv.z * k.z + xv.w * k.w;
    }
#pragma unroll
    for (int off = 16; off; off >>= 1) {
#pragma unroll
        for (int h = 0; h < 8; h++) a[h] += __shfl_xor_sync(0xffffffffu, a[h], off);
    }
    if (lane == 0) {
        g_hq[w] = make_float4(a[0], a[1], a[2], a[3]);
        float4 kk;
        kk.x = a[4] >= 0.f ? a[4] : NEG * a[4];
        kk.y = a[5] >= 0.f ? a[5] : NEG * a[5];
        kk.z = a[6] >= 0.f ? a[6] : NEG * a[6];
        kk.w = a[7] >= 0.f ? a[7] : NEG * a[7];
        g_kact[w] = kk;
    }
}

// ---------------- h_proj GEMM: [NN,128] = x[NN,128] @ Wl^T[128,128] + bl ---
// 128x128 tile per block, 256 threads, 8x8 register tile, k-major smem,
// fp32 compute/accumulate, fp16 store.
__global__ __launch_bounds__(256) void kgemm(const float* __restrict__ x,
                                             const float* __restrict__ Wl,
                                             const float* __restrict__ bl) {
    __shared__ float xs[32 * 132];
    __shared__ float ws[32 * 132];
    int nb = blockIdx.x * 128;
    int tid = threadIdx.x;
    int tx = tid & 15;   // outs:  o = tx*8 + oo
    int ty = tid >> 4;   // nodes: n = nb + ty*8 + nn
    float acc[8][8];
#pragma unroll
    for (int a = 0; a < 8; a++)
#pragma unroll
        for (int b = 0; b < 8; b++) acc[a][b] = 0.f;

    for (int kb = 0; kb < 32; kb += 8) {  // kb counts float4s (8 f4 = 32 floats)
#pragma unroll
        for (int it = 0; it < 4; it++) {
            int idx = tid + it * 256;      // 0..1023
            int row = idx >> 3, c = idx & 7;
            float4 v = make_float4(0.f, 0.f, 0.f, 0.f);
            if (nb + row < NN) v = ((const float4*)x)[(nb + row) * 32 + kb + c];
            xs[(4 * c + 0) * 132 + row] = v.x;
            xs[(4 * c + 1) * 132 + row] = v.y;
            xs[(4 * c + 2) * 132 + row] = v.z;
            xs[(4 * c + 3) * 132 + row] = v.w;
            float4 wv = ((const float4*)Wl)[row * 32 + kb + c];
            ws[(4 * c + 0) * 132 + row] = wv.x;
            ws[(4 * c + 1) * 132 + row] = wv.y;
            ws[(4 * c + 2) * 132 + row] = wv.z;
            ws[(4 * c + 3) * 132 + row] = wv.w;
        }
        __syncthreads();
#pragma unroll 8
        for (int k = 0; k < 32; k++) {
            float4 xa = *(const float4*)&xs[k * 132 + ty * 8];
            float4 xb = *(const float4*)&xs[k * 132 + ty * 8 + 4];
            float4 wa = *(const float4*)&ws[k * 132 + tx * 8];
            float4 wb = *(const float4*)&ws[k * 132 + tx * 8 + 4];
            float xr[8] = {xa.x, xa.y, xa.z, xa.w, xb.x, xb.y, xb.z, xb.w};
            float wr[8] = {wa.x, wa.y, wa.z, wa.w, wb.x, wb.y, wb.z, wb.w};
#pragma unroll
            for (int nn = 0; nn < 8; nn++)
#pragma unroll
                for (int oo = 0; oo < 8; oo++)
                    acc[nn][oo] = fmaf(xr[nn], wr[oo], acc[nn][oo]);
        }
        __syncthreads();
    }
    float b[8];
#pragma unroll
    for (int oo = 0; oo < 8; oo++) b[oo] = __ldg(&bl[tx * 8 + oo]);
#pragma unroll
    for (int nn = 0; nn < 8; nn++) {
        int n = nb + ty * 8 + nn;
        if (n >= NN) continue;
        uint4 pk;
        __half2 h01 = __floats2half2_rn(acc[nn][0] + b[0], acc[nn][1] + b[1]);
        __half2 h23 = __floats2half2_rn(acc[nn][2] + b[2], acc[nn][3] + b[3]);
        __half2 h45 = __floats2half2_rn(acc[nn][4] + b[4], acc[nn][5] + b[5]);
        __half2 h67 = __floats2half2_rn(acc[nn][6] + b[6], acc[nn][7] + b[7]);
        pk.x = *(unsigned*)&h01; pk.y = *(unsigned*)&h23;
        pk.z = *(unsigned*)&h45; pk.w = *(unsigned*)&h67;
        ((uint4*)g_hproj)[n * 16 + tx] = pk;
    }
}

// ---------------- q_agg: per-node sum of h_q over incoming edges -----------
__global__ __launch_bounds__(512) void kqagg() {
    int i = (blockIdx.x * blockDim.x + threadIdx.x) >> 5;
    int lane = threadIdx.x & 31;
    if (i >= NN) return;
    int deg = g_deg[i];
    int degE = min(deg, W);
    float4 a = make_float4(0.f, 0.f, 0.f, 0.f);
    for (int k = lane; k < degE; k += 32) {
        float4 q = g_hq[g_ell[i * W + k]];
        a.x += q.x; a.y += q.y; a.z += q.z; a.w += q.w;
    }
    if (deg > W) {  // insurance path (never taken for this input)
        int n = min(g_novf, NOVF);
        for (int t = lane; t < n; t += 32) {
            if (g_ovf_r[t] == i) {
                float4 q = g_hq[g_ovf_c[t]];
                a.x += q.x; a.y += q.y; a.z += q.z; a.w += q.w;
            }
        }
    }
#pragma unroll
    for (int off = 16; off; off >>= 1) {
        a.x += __shfl_xor_sync(0xffffffffu, a.x, off);
        a.y += __shfl_xor_sync(0xffffffffu, a.y, off);
        a.z += __shfl_xor_sync(0xffffffffu, a.z, off);
        a.w += __shfl_xor_sync(0xffffffffu, a.w, off);
    }
    if (lane == 0) g_qagg[i] = a;
}

// ---------------- fused softmax + aggregation + leaky ----------------------
__global__ __launch_bounds__(512) void kmain(float* __restrict__ out) {
    int i = (blockIdx.x * blockDim.x + threadIdx.x) >> 5;
    int lane = threadIdx.x & 31;
    if (i >= NN) return;
    int deg = g_deg[i];
    int degE = min(deg, W);
    float4 kc = g_kact[i];

    // pass 1: gather q_agg, scores into registers, segment max per head
    float4 sc[4];
    int col[4];
    float m0 = -1e30f, m1 = -1e30f, m2 = -1e30f, m3 = -1e30f;
#pragma unroll
    for (int ch = 0; ch < 4; ch++) {
        int k = ch * 32 + lane;
        sc[ch] = make_float4(-1e30f, -1e30f, -1e30f, -1e30f);
        col[ch] = 0;
        if (ch * 32 < degE && k < degE) {
            int c = __ldg(&g_ell[i * W + k]);
            col[ch] = c;
            float4 q = g_qagg[c];
            sc[ch].x = kc.x * q.x; sc[ch].y = kc.y * q.y;
            sc[ch].z = kc.z * q.z; sc[ch].w = kc.w * q.w;
        }
        m0 = fmaxf(m0, sc[ch].x); m1 = fmaxf(m1, sc[ch].y);
        m2 = fmaxf(m2, sc[ch].z); m3 = fmaxf(m3, sc[ch].w);
    }
    if (deg > W) {  // insurance
        int n = min(g_novf, NOVF);
        for (int t = lane; t < n; t += 32) {
            if (g_ovf_r[t] == i) {
                float4 q = g_qagg[g_ovf_c[t]];
                m0 = fmaxf(m0, kc.x * q.x); m1 = fmaxf(m1, kc.y * q.y);
                m2 = fmaxf(m2, kc.z * q.z); m3 = fmaxf(m3, kc.w * q.w);
            }
        }
    }
#pragma unroll
    for (int off = 16; off; off >>= 1) {
        m0 = fmaxf(m0, __shfl_xor_sync(0xffffffffu, m0, off));
        m1 = fmaxf(m1, __shfl_xor_sync(0xffffffffu, m1, off));
        m2 = fmaxf(m2, __shfl_xor_sync(0xffffffffu, m2, off));
        m3 = fmaxf(m3, __shfl_xor_sync(0xffffffffu, m3, off));
    }

    // pass 2: exp in registers, accumulate sums
    float s0 = 0.f, s1 = 0.f, s2 = 0.f, s3 = 0.f;
#pragma unroll
    for (int ch = 0; ch < 4; ch++) {
        sc[ch].x = __expf(sc[ch].x - m0); sc[ch].y = __expf(sc[ch].y - m1);
        sc[ch].z = __expf(sc[ch].z - m2); sc[ch].w = __expf(sc[ch].w - m3);
        int k = ch * 32 + lane;
        if (k >= degE) sc[ch] = make_float4(0.f, 0.f, 0.f, 0.f);
        s0 += sc[ch].x; s1 += sc[ch].y; s2 += sc[ch].z; s3 += sc[ch].w;
    }
    if (deg > W) {  // insurance
        int n = min(g_novf, NOVF);
        for (int t = lane; t < n; t += 32) {
            if (g_ovf_r[t] == i) {
                float4 q = g_qagg[g_ovf_c[t]];
                s0 += __expf(kc.x * q.x - m0); s1 += __expf(kc.y * q.y - m1);
                s2 += __expf(kc.z * q.z - m2); s3 += __expf(kc.w * q.w - m3);
            }
        }
    }
#pragma unroll
    for (int off = 16; off; off >>= 1) {
        s0 += __shfl_xor_sync(0xffffffffu, s0, off);
        s1 += __shfl_xor_sync(0xffffffffu, s1, off);
        s2 += __shfl_xor_sync(0xffffffffu, s2, off);
        s3 += __shfl_xor_sync(0xffffffffu, s3, off);
    }
    float i0 = 0.25f / (s0 + 1e-8f);
    float i1 = 0.25f / (s1 + 1e-8f);
    float i2 = 0.25f / (s2 + 1e-8f);
    float i3 = 0.25f / (s3 + 1e-8f);

    // pass 3: weighted aggregation of fp16 h_proj[col]
    float4 acc = make_float4(0.f, 0.f, 0.f, 0.f);
#pragma unroll
    for (int ch = 0; ch < 4; ch++) {
        int base = ch * 32;
        if (base >= degE) break;
        float w = sc[ch].x * i0 + sc[ch].y * i1 + sc[ch].z * i2 + sc[ch].w * i3;
        int cnt = min(32, degE - base);
#pragma unroll 4
        for (int jj = 0; jj < cnt; jj++) {
            int cc = __shfl_sync(0xffffffffu, col[ch], jj);
            float ww = __shfl_sync(0xffffffffu, w, jj);
            uint2 hv = ((const uint2*)g_hproj)[cc * 32 + lane];
            float2 f01 = __half22float2(*(__half2*)&hv.x);
            float2 f23 = __half22float2(*(__half2*)&hv.y);
            acc.x = fmaf(ww, f01.x, acc.x);
            acc.y = fmaf(ww, f01.y, acc.y);
            acc.z = fmaf(ww, f23.x, acc.z);
            acc.w = fmaf(ww, f23.y, acc.w);
        }
    }
    if (deg > W) {  // insurance: scalar broadcast over overflow list
        int n = min(g_novf, NOVF);
        for (int t = 0; t < n; t++) {
            int rr = g_ovf_r[t];
            if (rr == i) {
                int cc = g_ovf_c[t];
                float4 q = g_qagg[cc];
                float ww = __expf(kc.x * q.x - m0) * i0 + __expf(kc.y * q.y - m1) * i1 +
                           __expf(kc.z * q.z - m2) * i2 + __expf(kc.w * q.w - m3) * i3;
                uint2 hv = ((const uint2*)g_hproj)[cc * 32 + lane];
                float2 f01 = __half22float2(*(__half2*)&hv.x);
                float2 f23 = __half22float2(*(__half2*)&hv.y);
                acc.x = fmaf(ww, f01.x, acc.x);
                acc.y = fmaf(ww, f01.y, acc.y);
                acc.z = fmaf(ww, f23.x, acc.z);
                acc.w = fmaf(ww, f23.y, acc.w);
            }
        }
    }
    float4 o;
    o.x = acc.x >= 0.f ? acc.x : NEG * acc.x;
    o.y = acc.y >= 0.f ? acc.y : NEG * acc.y;
    o.z = acc.z >= 0.f ? acc.z : NEG * acc.z;
    o.w = acc.w >= 0.f ? acc.w : NEG * acc.w;
    ((float4*)out)[i * 32 + lane] = o;
}

// ---------------- launch ----------------
extern "C" void kernel_launch(void* const* d_in, const int* in_sizes, int n_in,
                              void* d_out, int out_size) {
    const float* x  = (const float*)d_in[0];
    const int*   ei = (const int*)d_in[1];
    const float* Wq = (const float*)d_in[2];
    const float* Wk = (const float*)d_in[3];
    const float* Wl = (const float*)d_in[4];
    const float* bl = (const float*)d_in[5];
    float* out = (float*)d_out;

    kzero<<<(NN + 255) / 256, 256>>>();
    kbuild<<<(NE / 4 + 255) / 256, 256>>>(ei);
    kprojsmall<<<(NN * 32 + 255) / 256, 256>>>(x, Wq, Wk);
    kgemm<<<(NN + 127) / 128, 256>>>(x, Wl, bl);
    kqagg<<<(NN * 32 + 511) / 512, 512>>>();
    kmain<<<(NN * 32 + 511) / 512, 512>>>(out);
}

// round 8
// speedup vs baseline: 1.2085x; 1.2085x over previous
#include <cuda_runtime.h>
#include <cuda_fp16.h>

#define NN 50000
#define NE 1600000
#define NEG 0.2f
#define W 128           // ELL width (in-degree is Poisson(32); max ~65)
#define NOVF 65536      // overflow insurance capacity

// ---------------- scratch (device globals; no allocation allowed) ----------
__device__ float4 g_hq[NN];          // per-node h_q (4 heads)
__device__ float4 g_kact[NN];        // per-node leaky(x@Wk^T)
__device__ float4 g_qagg[NN];        // per-node aggregated q
__device__ float  g_hproj[NN * 128]; // per-node x@Wl^T + bl (fp32)
__device__ int    g_deg[NN];
__device__ int    g_ell[NN * W];     // ELL adjacency: cols of incoming edges
__device__ int    g_ovf_r[NOVF];
__device__ int    g_ovf_c[NOVF];
__device__ int    g_novf;

// ---------------- init ----------------
__global__ void kzero() {
    int i = blockIdx.x * blockDim.x + threadIdx.x;
    if (i < NN) g_deg[i] = 0;
    if (i == 0) g_novf = 0;
}

// ---------------- single-pass ELL build, 4 edges/thread for MLP ------------
__global__ void kbuild(const int* __restrict__ ei) {
    int t = blockIdx.x * blockDim.x + threadIdx.x;
    int e0 = t * 4;
    if (e0 >= NE) return;
    int4 r4 = *(const int4*)&ei[e0];
    int4 c4 = *(const int4*)&ei[NE + e0];
    int rr[4] = {r4.x, r4.y, r4.z, r4.w};
    int cc[4] = {c4.x, c4.y, c4.z, c4.w};
    int pp[4];
#pragma unroll
    for (int j = 0; j < 4; j++) pp[j] = atomicAdd(&g_deg[rr[j]], 1);
#pragma unroll
    for (int j = 0; j < 4; j++) {
        if (pp[j] < W) {
            g_ell[rr[j] * W + pp[j]] = cc[j];
        } else {
            int o = atomicAdd(&g_novf, 1);
            if (o < NOVF) { g_ovf_r[o] = rr[j]; g_ovf_c[o] = cc[j]; }
        }
    }
}

// ---------------- per-node small projections: h_q, k_act -------------------
__global__ void kprojsmall(const float* __restrict__ x,
                           const float* __restrict__ Wq,
                           const float* __restrict__ Wk) {
    int w = (blockIdx.x * blockDim.x + threadIdx.x) >> 5;
    int lane = threadIdx.x & 31;
    if (w >= NN) return;
    float4 xv = ((const float4*)x)[w * 32 + lane];
    float a[8];
#pragma unroll
    for (int h = 0; h < 4; h++) {
        float4 q = ((const float4*)Wq)[h * 32 + lane];
        float4 k = ((const float4*)Wk)[h * 32 + lane];
        a[h]     = xv.x * q.x + xv.y * q.y + xv.z * q.z + xv.w * q.w;
        a[4 + h] = xv.x * k.x + xv.y * k.y + xv.z * k.z + xv.w * k.w;
    }
#pragma unroll
    for (int off = 16; off; off >>= 1) {
#pragma unroll
        for (int h = 0; h < 8; h++) a[h] += __shfl_xor_sync(0xffffffffu, a[h], off);
    }
    if (lane == 0) {
        g_hq[w] = make_float4(a[0], a[1], a[2], a[3]);
        float4 kk;
        kk.x = a[4] >= 0.f ? a[4] : NEG * a[4];
        kk.y = a[5] >= 0.f ? a[5] : NEG * a[5];
        kk.z = a[6] >= 0.f ? a[6] : NEG * a[6];
        kk.w = a[7] >= 0.f ? a[7] : NEG * a[7];
        g_kact[w] = kk;
    }
}

// ---------------- h_proj GEMM via HMMA (fp16 in, fp32 acc) -----------------
// Block tile 128 nodes x 128 outs. 8 warps: warp_m = wid&3 (32 rows),
// warp_n = wid>>2 (64 cols). K staged in two 64-wide fp16 smem chunks,
// row stride 72 halfs (bank-stride 4 -> conflict-free fragment loads).
// mma.sync.m16n8k16.row.col: fragments loaded directly as half2 (both
// A=x and B=Wl^T are k-contiguous in memory).
#define XS_STRIDE 72
__global__ __launch_bounds__(256) void kgemm(const float* __restrict__ x,
                                             const float* __restrict__ Wl,
                                             const float* __restrict__ bl) {
    __shared__ __half xs[128 * XS_STRIDE];
    __shared__ __half ws[128 * XS_STRIDE];
    int nb = blockIdx.x * 128;
    int tid = threadIdx.x;
    int wid = tid >> 5;
    int lane = tid & 31;
    int warp_m = wid & 3;
    int warp_n = wid >> 2;
    int group = lane >> 2;        // 0..7
    int qk = (lane & 3) * 2;      // 0,2,4,6

    float acc[2][8][4];
#pragma unroll
    for (int mi = 0; mi < 2; mi++)
#pragma unroll
        for (int ni = 0; ni < 8; ni++)
#pragma unroll
            for (int r = 0; r < 4; r++) acc[mi][ni][r] = 0.f;

    for (int ko = 0; ko < 2; ko++) {          // two 64-wide K chunks
        // stage: 128 rows x 16 float4 per tensor
#pragma unroll
        for (int it = 0; it < 8; it++) {
            int idx = tid + it * 256;          // 0..2047
            int row = idx >> 4, c = idx & 15;
            float4 v = make_float4(0.f, 0.f, 0.f, 0.f);
            if (nb + row < NN) v = ((const float4*)x)[(nb + row) * 32 + ko * 16 + c];
            __half2 h01 = __floats2half2_rn(v.x, v.y);
            __half2 h23 = __floats2half2_rn(v.z, v.w);
            uint2 pk = make_uint2(*(unsigned*)&h01, *(unsigned*)&h23);
            *(uint2*)&xs[row * XS_STRIDE + c * 4] = pk;
            float4 wv = ((const float4*)Wl)[row * 32 + ko * 16 + c];
            __half2 w01 = __floats2half2_rn(wv.x, wv.y);
            __half2 w23 = __floats2half2_rn(wv.z, wv.w);
            uint2 wp = make_uint2(*(unsigned*)&w01, *(unsigned*)&w23);
            *(uint2*)&ws[row * XS_STRIDE + c * 4] = wp;
        }
        __syncthreads();
#pragma unroll
        for (int kc = 0; kc < 4; kc++) {      // four k16 sub-chunks
            unsigned a[2][4];
#pragma unroll
            for (int mi = 0; mi < 2; mi++) {
                int r0 = warp_m * 32 + mi * 16 + group;
                int base = r0 * XS_STRIDE + kc * 16 + qk;
                a[mi][0] = *(const unsigned*)&xs[base];
                a[mi][1] = *(const unsigned*)&xs[base + 8 * XS_STRIDE];
                a[mi][2] = *(const unsigned*)&xs[base + 8];
                a[mi][3] = *(const unsigned*)&xs[base + 8 * XS_STRIDE + 8];
            }
#pragma unroll
            for (int ni = 0; ni < 8; ni++) {
                int o = warp_n * 64 + ni * 8 + group;
                int wbase = o * XS_STRIDE + kc * 16 + qk;
                unsigned b0 = *(const unsigned*)&ws[wbase];
                unsigned b1 = *(const unsigned*)&ws[wbase + 8];
#pragma unroll
                for (int mi = 0; mi < 2; mi++) {
                    asm volatile(
                        "mma.sync.aligned.m16n8k16.row.col.f32.f16.f16.f32 "
                        "{%0,%1,%2,%3}, {%4,%5,%6,%7}, {%8,%9}, {%0,%1,%2,%3};"
                        : "+f"(acc[mi][ni][0]), "+f"(acc[mi][ni][1]),
                          "+f"(acc[mi][ni][2]), "+f"(acc[mi][ni][3])
                        : "r"(a[mi][0]), "r"(a[mi][1]), "r"(a[mi][2]), "r"(a[mi][3]),
                          "r"(b0), "r"(b1));
                }
            }
        }
        __syncthreads();
    }
    // epilogue: add bias, store fp32
#pragma unroll
    for (int ni = 0; ni < 8; ni++) {
        int o = warp_n * 64 + ni * 8 + qk;
        float b0 = __ldg(&bl[o]);
        float b1 = __ldg(&bl[o + 1]);
#pragma unroll
        for (int mi = 0; mi < 2; mi++) {
            int r = nb + warp_m * 32 + mi * 16 + group;
            if (r < NN)
                *(float2*)&g_hproj[r * 128 + o] =
                    make_float2(acc[mi][ni][0] + b0, acc[mi][ni][1] + b1);
            if (r + 8 < NN)
                *(float2*)&g_hproj[(r + 8) * 128 + o] =
                    make_float2(acc[mi][ni][2] + b0, acc[mi][ni][3] + b1);
        }
    }
}

// ---------------- q_agg: per-node sum of h_q over incoming edges -----------
__global__ __launch_bounds__(512) void kqagg() {
    int i = (blockIdx.x * blockDim.x + threadIdx.x) >> 5;
    int lane = threadIdx.x & 31;
    if (i >= NN) return;
    int deg = g_deg[i];
    int degE = min(deg, W);
    float4 a = make_float4(0.f, 0.f, 0.f, 0.f);
    for (int k = lane; k < degE; k += 32) {
        float4 q = g_hq[g_ell[i * W + k]];
        a.x += q.x; a.y += q.y; a.z += q.z; a.w += q.w;
    }
    if (deg > W) {  // insurance path (never taken for this input)
        int n = min(g_novf, NOVF);
        for (int t = lane; t < n; t += 32) {
            if (g_ovf_r[t] == i) {
                float4 q = g_hq[g_ovf_c[t]];
                a.x += q.x; a.y += q.y; a.z += q.z; a.w += q.w;
            }
        }
    }
#pragma unroll
    for (int off = 16; off; off >>= 1) {
        a.x += __shfl_xor_sync(0xffffffffu, a.x, off);
        a.y += __shfl_xor_sync(0xffffffffu, a.y, off);
        a.z += __shfl_xor_sync(0xffffffffu, a.z, off);
        a.w += __shfl_xor_sync(0xffffffffu, a.w, off);
    }
    if (lane == 0) g_qagg[i] = a;
}

// ---------------- fused softmax + aggregation + leaky ----------------------
__global__ __launch_bounds__(512) void kmain(float* __restrict__ out) {
    int i = (blockIdx.x * blockDim.x + threadIdx.x) >> 5;
    int lane = threadIdx.x & 31;
    if (i >= NN) return;
    int deg = g_deg[i];
    int degE = min(deg, W);
    float4 kc = g_kact[i];

    // pass 1: gather q_agg, scores into registers, segment max per head
    float4 sc[4];
    int col[4];
    float m0 = -1e30f, m1 = -1e30f, m2 = -1e30f, m3 = -1e30f;
#pragma unroll
    for (int ch = 0; ch < 4; ch++) {
        int k = ch * 32 + lane;
        sc[ch] = make_float4(-1e30f, -1e30f, -1e30f, -1e30f);
        col[ch] = 0;
        if (ch * 32 < degE && k < degE) {
            int c = __ldg(&g_ell[i * W + k]);
            col[ch] = c;
            float4 q = g_qagg[c];
            sc[ch].x = kc.x * q.x; sc[ch].y = kc.y * q.y;
            sc[ch].z = kc.z * q.z; sc[ch].w = kc.w * q.w;
        }
        m0 = fmaxf(m0, sc[ch].x); m1 = fmaxf(m1, sc[ch].y);
        m2 = fmaxf(m2, sc[ch].z); m3 = fmaxf(m3, sc[ch].w);
    }
    if (deg > W) {  // insurance
        int n = min(g_novf, NOVF);
        for (int t = lane; t < n; t += 32) {
            if (g_ovf_r[t] == i) {
                float4 q = g_qagg[g_ovf_c[t]];
                m0 = fmaxf(m0, kc.x * q.x); m1 = fmaxf(m1, kc.y * q.y);
                m2 = fmaxf(m2, kc.z * q.z); m3 = fmaxf(m3, kc.w * q.w);
            }
        }
    }
#pragma unroll
    for (int off = 16; off; off >>= 1) {
        m0 = fmaxf(m0, __shfl_xor_sync(0xffffffffu, m0, off));
        m1 = fmaxf(m1, __shfl_xor_sync(0xffffffffu, m1, off));
        m2 = fmaxf(m2, __shfl_xor_sync(0xffffffffu, m2, off));
        m3 = fmaxf(m3, __shfl_xor_sync(0xffffffffu, m3, off));
    }

    // pass 2: exp in registers, accumulate sums
    float s0 = 0.f, s1 = 0.f, s2 = 0.f, s3 = 0.f;
#pragma unroll
    for (int ch = 0; ch < 4; ch++) {
        sc[ch].x = __expf(sc[ch].x - m0); sc[ch].y = __expf(sc[ch].y - m1);
        sc[ch].z = __expf(sc[ch].z - m2); sc[ch].w = __expf(sc[ch].w - m3);
        int k = ch * 32 + lane;
        if (k >= degE) sc[ch] = make_float4(0.f, 0.f, 0.f, 0.f);
        s0 += sc[ch].x; s1 += sc[ch].y; s2 += sc[ch].z; s3 += sc[ch].w;
    }
    if (deg > W) {  // insurance
        int n = min(g_novf, NOVF);
        for (int t = lane; t < n; t += 32) {
            if (g_ovf_r[t] == i) {
                float4 q = g_qagg[g_ovf_c[t]];
                s0 += __expf(kc.x * q.x - m0); s1 += __expf(kc.y * q.y - m1);
                s2 += __expf(kc.z * q.z - m2); s3 += __expf(kc.w * q.w - m3);
            }
        }
    }
#pragma unroll
    for (int off = 16; off; off >>= 1) {
        s0 += __shfl_xor_sync(0xffffffffu, s0, off);
        s1 += __shfl_xor_sync(0xffffffffu, s1, off);
        s2 += __shfl_xor_sync(0xffffffffu, s2, off);
        s3 += __shfl_xor_sync(0xffffffffu, s3, off);
    }
    float i0 = 0.25f / (s0 + 1e-8f);
    float i1 = 0.25f / (s1 + 1e-8f);
    float i2 = 0.25f / (s2 + 1e-8f);
    float i3 = 0.25f / (s3 + 1e-8f);

    // pass 3: weighted aggregation of h_proj[col]
    float4 acc = make_float4(0.f, 0.f, 0.f, 0.f);
#pragma unroll
    for (int ch = 0; ch < 4; ch++) {
        int base = ch * 32;
        if (base >= degE) break;
        float w = sc[ch].x * i0 + sc[ch].y * i1 + sc[ch].z * i2 + sc[ch].w * i3;
        int cnt = min(32, degE - base);
#pragma unroll 4
        for (int jj = 0; jj < cnt; jj++) {
            int cc = __shfl_sync(0xffffffffu, col[ch], jj);
            float ww = __shfl_sync(0xffffffffu, w, jj);
            float4 hp = ((const float4*)g_hproj)[cc * 32 + lane];
            acc.x = fmaf(ww, hp.x, acc.x);
            acc.y = fmaf(ww, hp.y, acc.y);
            acc.z = fmaf(ww, hp.z, acc.z);
            acc.w = fmaf(ww, hp.w, acc.w);
        }
    }
    if (deg > W) {  // insurance: scalar broadcast over overflow list
        int n = min(g_novf, NOVF);
        for (int t = 0; t < n; t++) {
            int rr = g_ovf_r[t];
            if (rr == i) {
                int cc = g_ovf_c[t];
                float4 q = g_qagg[cc];
                float ww = __expf(kc.x * q.x - m0) * i0 + __expf(kc.y * q.y - m1) * i1 +
                           __expf(kc.z * q.z - m2) * i2 + __expf(kc.w * q.w - m3) * i3;
                float4 hp = ((const float4*)g_hproj)[cc * 32 + lane];
                acc.x = fmaf(ww, hp.x, acc.x);
                acc.y = fmaf(ww, hp.y, acc.y);
                acc.z = fmaf(ww, hp.z, acc.z);
                acc.w = fmaf(ww, hp.w, acc.w);
            }
        }
    }
    float4 o;
    o.x = acc.x >= 0.f ? acc.x : NEG * acc.x;
    o.y = acc.y >= 0.f ? acc.y : NEG * acc.y;
    o.z = acc.z >= 0.f ? acc.z : NEG * acc.z;
    o.w = acc.w >= 0.f ? acc.w : NEG * acc.w;
    ((float4*)out)[i * 32 + lane] = o;
}

// ---------------- launch ----------------
extern "C" void kernel_launch(void* const* d_in, const int* in_sizes, int n_in,
                              void* d_out, int out_size) {
    const float* x  = (const float*)d_in[0];
    const int*   ei = (const int*)d_in[1];
    const float* Wq = (const float*)d_in[2];
    const float* Wk = (const float*)d_in[3];
    const float* Wl = (const float*)d_in[4];
    const float* bl = (const float*)d_in[5];
    float* out = (float*)d_out;

    kzero<<<(NN + 255) / 256, 256>>>();
    kbuild<<<(NE / 4 + 255) / 256, 256>>>(ei);
    kprojsmall<<<(NN * 32 + 255) / 256, 256>>>(x, Wq, Wk);
    kgemm<<<(NN + 127) / 128, 256>>>(x, Wl, bl);
    kqagg<<<(NN * 32 + 511) / 512, 512>>>();
    kmain<<<(NN * 32 + 511) / 512, 512>>>(out);
}

// round 9
// speedup vs baseline: 1.2087x; 1.0002x over previous
#include <cuda_runtime.h>
#include <cuda_fp16.h>

#define NN 50000
#define NE 1600000
#define NEG 0.2f
#define W 128           // ELL width (in-degree is Poisson(32); max ~65)
#define NOVF 65536      // overflow insurance capacity

// ---------------- scratch (device globals; no allocation allowed) ----------
__device__ float4 g_hq[NN];          // per-node h_q (4 heads)
__device__ float4 g_kact[NN];        // per-node leaky(x@Wk^T)
__device__ float4 g_qagg[NN];        // per-node aggregated q
__device__ __half g_hproj[NN * 128]; // per-node x@Wl^T + bl (fp16 storage)
__device__ int    g_deg[NN];
__device__ int    g_ell[NN * W];     // ELL adjacency: cols of incoming edges
__device__ int    g_ovf_r[NOVF];
__device__ int    g_ovf_c[NOVF];
__device__ int    g_novf;

// ---------------- init ----------------
__global__ void kzero() {
    int i = blockIdx.x * blockDim.x + threadIdx.x;
    if (i < NN) g_deg[i] = 0;
    if (i == 0) g_novf = 0;
}

// ---------------- single-pass ELL build, 4 edges/thread for MLP ------------
__global__ void kbuild(const int* __restrict__ ei) {
    int t = blockIdx.x * blockDim.x + threadIdx.x;
    int e0 = t * 4;
    if (e0 >= NE) return;
    int4 r4 = *(const int4*)&ei[e0];
    int4 c4 = *(const int4*)&ei[NE + e0];
    int rr[4] = {r4.x, r4.y, r4.z, r4.w};
    int cc[4] = {c4.x, c4.y, c4.z, c4.w};
    int pp[4];
#pragma unroll
    for (int j = 0; j < 4; j++) pp[j] = atomicAdd(&g_deg[rr[j]], 1);
#pragma unroll
    for (int j = 0; j < 4; j++) {
        if (pp[j] < W) {
            g_ell[rr[j] * W + pp[j]] = cc[j];
        } else {
            int o = atomicAdd(&g_novf, 1);
            if (o < NOVF) { g_ovf_r[o] = rr[j]; g_ovf_c[o] = cc[j]; }
        }
    }
}

// ---------------- per-node small projections: h_q, k_act -------------------
__global__ void kprojsmall(const float* __restrict__ x,
                           const float* __restrict__ Wq,
                           const float* __restrict__ Wk) {
    int w = (blockIdx.x * blockDim.x + threadIdx.x) >> 5;
    int lane = threadIdx.x & 31;
    if (w >= NN) return;
    float4 xv = ((const float4*)x)[w * 32 + lane];
    float a[8];
#pragma unroll
    for (int h = 0; h < 4; h++) {
        float4 q = ((const float4*)Wq)[h * 32 + lane];
        float4 k = ((const float4*)Wk)[h * 32 + lane];
        a[h]     = xv.x * q.x + xv.y * q.y + xv.z * q.z + xv.w * q.w;
        a[4 + h] = xv.x * k.x + xv.y * k.y + xv.z * k.z + xv.w * k.w;
    }
#pragma unroll
    for (int off = 16; off; off >>= 1) {
#pragma unroll
        for (int h = 0; h < 8; h++) a[h] += __shfl_xor_sync(0xffffffffu, a[h], off);
    }
    if (lane == 0) {
        g_hq[w] = make_float4(a[0], a[1], a[2], a[3]);
        float4 kk;
        kk.x = a[4] >= 0.f ? a[4] : NEG * a[4];
        kk.y = a[5] >= 0.f ? a[5] : NEG * a[5];
        kk.z = a[6] >= 0.f ? a[6] : NEG * a[6];
        kk.w = a[7] >= 0.f ? a[7] : NEG * a[7];
        g_kact[w] = kk;
    }
}

// ---------------- h_proj GEMM via HMMA (fp16 in, fp32 acc, fp16 store) -----
#define XS_STRIDE 72
__global__ __launch_bounds__(256) void kgemm(const float* __restrict__ x,
                                             const float* __restrict__ Wl,
                                             const float* __restrict__ bl) {
    __shared__ __half xs[128 * XS_STRIDE];
    __shared__ __half ws[128 * XS_STRIDE];
    int nb = blockIdx.x * 128;
    int tid = threadIdx.x;
    int wid = tid >> 5;
    int lane = tid & 31;
    int warp_m = wid & 3;
    int warp_n = wid >> 2;
    int group = lane >> 2;        // 0..7
    int qk = (lane & 3) * 2;      // 0,2,4,6

    float acc[2][8][4];
#pragma unroll
    for (int mi = 0; mi < 2; mi++)
#pragma unroll
        for (int ni = 0; ni < 8; ni++)
#pragma unroll
            for (int r = 0; r < 4; r++) acc[mi][ni][r] = 0.f;

    for (int ko = 0; ko < 2; ko++) {          // two 64-wide K chunks
#pragma unroll
        for (int it = 0; it < 8; it++) {
            int idx = tid + it * 256;          // 0..2047
            int row = idx >> 4, c = idx & 15;
            float4 v = make_float4(0.f, 0.f, 0.f, 0.f);
            if (nb + row < NN) v = ((const float4*)x)[(nb + row) * 32 + ko * 16 + c];
            __half2 h01 = __floats2half2_rn(v.x, v.y);
            __half2 h23 = __floats2half2_rn(v.z, v.w);
            uint2 pk = make_uint2(*(unsigned*)&h01, *(unsigned*)&h23);
            *(uint2*)&xs[row * XS_STRIDE + c * 4] = pk;
            float4 wv = ((const float4*)Wl)[row * 32 + ko * 16 + c];
            __half2 w01 = __floats2half2_rn(wv.x, wv.y);
            __half2 w23 = __floats2half2_rn(wv.z, wv.w);
            uint2 wp = make_uint2(*(unsigned*)&w01, *(unsigned*)&w23);
            *(uint2*)&ws[row * XS_STRIDE + c * 4] = wp;
        }
        __syncthreads();
#pragma unroll
        for (int kc = 0; kc < 4; kc++) {      // four k16 sub-chunks
            unsigned a[2][4];
#pragma unroll
            for (int mi = 0; mi < 2; mi++) {
                int r0 = warp_m * 32 + mi * 16 + group;
                int base = r0 * XS_STRIDE + kc * 16 + qk;
                a[mi][0] = *(const unsigned*)&xs[base];
                a[mi][1] = *(const unsigned*)&xs[base + 8 * XS_STRIDE];
                a[mi][2] = *(const unsigned*)&xs[base + 8];
                a[mi][3] = *(const unsigned*)&xs[base + 8 * XS_STRIDE + 8];
            }
#pragma unroll
            for (int ni = 0; ni < 8; ni++) {
                int o = warp_n * 64 + ni * 8 + group;
                int wbase = o * XS_STRIDE + kc * 16 + qk;
                unsigned b0 = *(const unsigned*)&ws[wbase];
                unsigned b1 = *(const unsigned*)&ws[wbase + 8];
#pragma unroll
                for (int mi = 0; mi < 2; mi++) {
                    asm volatile(
                        "mma.sync.aligned.m16n8k16.row.col.f32.f16.f16.f32 "
                        "{%0,%1,%2,%3}, {%4,%5,%6,%7}, {%8,%9}, {%0,%1,%2,%3};"
                        : "+f"(acc[mi][ni][0]), "+f"(acc[mi][ni][1]),
                          "+f"(acc[mi][ni][2]), "+f"(acc[mi][ni][3])
                        : "r"(a[mi][0]), "r"(a[mi][1]), "r"(a[mi][2]), "r"(a[mi][3]),
                          "r"(b0), "r"(b1));
                }
            }
        }
        __syncthreads();
    }
    // epilogue: add bias, store fp16
#pragma unroll
    for (int ni = 0; ni < 8; ni++) {
        int o = warp_n * 64 + ni * 8 + qk;
        float b0 = __ldg(&bl[o]);
        float b1 = __ldg(&bl[o + 1]);
#pragma unroll
        for (int mi = 0; mi < 2; mi++) {
            int r = nb + warp_m * 32 + mi * 16 + group;
            if (r < NN) {
                __half2 h = __floats2half2_rn(acc[mi][ni][0] + b0, acc[mi][ni][1] + b1);
                *(__half2*)&g_hproj[r * 128 + o] = h;
            }
            if (r + 8 < NN) {
                __half2 h = __floats2half2_rn(acc[mi][ni][2] + b0, acc[mi][ni][3] + b1);
                *(__half2*)&g_hproj[(r + 8) * 128 + o] = h;
            }
        }
    }
}

// ---------------- q_agg: per-node sum of h_q over incoming edges -----------
__global__ __launch_bounds__(512) void kqagg() {
    int i = (blockIdx.x * blockDim.x + threadIdx.x) >> 5;
    int lane = threadIdx.x & 31;
    if (i >= NN) return;
    int deg = g_deg[i];
    int degE = min(deg, W);
    float4 a = make_float4(0.f, 0.f, 0.f, 0.f);
    for (int k = lane; k < degE; k += 32) {
        float4 q = g_hq[g_ell[i * W + k]];
        a.x += q.x; a.y += q.y; a.z += q.z; a.w += q.w;
    }
    if (deg > W) {  // insurance path (never taken for this input)
        int n = min(g_novf, NOVF);
        for (int t = lane; t < n; t += 32) {
            if (g_ovf_r[t] == i) {
                float4 q = g_hq[g_ovf_c[t]];
                a.x += q.x; a.y += q.y; a.z += q.z; a.w += q.w;
            }
        }
    }
#pragma unroll
    for (int off = 16; off; off >>= 1) {
        a.x += __shfl_xor_sync(0xffffffffu, a.x, off);
        a.y += __shfl_xor_sync(0xffffffffu, a.y, off);
        a.z += __shfl_xor_sync(0xffffffffu, a.z, off);
        a.w += __shfl_xor_sync(0xffffffffu, a.w, off);
    }
    if (lane == 0) g_qagg[i] = a;
}

// ---------------- fused softmax + aggregation + leaky ----------------------
__global__ __launch_bounds__(256) void kmain(float* __restrict__ out) {
    int i = (blockIdx.x * blockDim.x + threadIdx.x) >> 5;
    int lane = threadIdx.x & 31;
    if (i >= NN) return;
    int deg = g_deg[i];
    int degE = min(deg, W);
    float4 kc = g_kact[i];

    // pass 1: gather q_agg, scores into registers, segment max per head
    float4 sc[4];
    int col[4];
    float m0 = -1e30f, m1 = -1e30f, m2 = -1e30f, m3 = -1e30f;
#pragma unroll
    for (int ch = 0; ch < 4; ch++) {
        sc[ch] = make_float4(-1e30f, -1e30f, -1e30f, -1e30f);
        col[ch] = 0;
    }
#pragma unroll
    for (int ch = 0; ch < 4; ch++) {
        if (ch * 32 >= degE) break;
        int k = ch * 32 + lane;
        if (k < degE) {
            int c = __ldg(&g_ell[i * W + k]);
            col[ch] = c;
            float4 q = g_qagg[c];
            sc[ch].x = kc.x * q.x; sc[ch].y = kc.y * q.y;
            sc[ch].z = kc.z * q.z; sc[ch].w = kc.w * q.w;
        }
        m0 = fmaxf(m0, sc[ch].x); m1 = fmaxf(m1, sc[ch].y);
        m2 = fmaxf(m2, sc[ch].z); m3 = fmaxf(m3, sc[ch].w);
    }
    if (deg > W) {  // insurance
        int n = min(g_novf, NOVF);
        for (int t = lane; t < n; t += 32) {
            if (g_ovf_r[t] == i) {
                float4 q = g_qagg[g_ovf_c[t]];
                m0 = fmaxf(m0, kc.x * q.x); m1 = fmaxf(m1, kc.y * q.y);
                m2 = fmaxf(m2, kc.z * q.z); m3 = fmaxf(m3, kc.w * q.w);
            }
        }
    }
#pragma unroll
    for (int off = 16; off; off >>= 1) {
        m0 = fmaxf(m0, __shfl_xor_sync(0xffffffffu, m0, off));
        m1 = fmaxf(m1, __shfl_xor_sync(0xffffffffu, m1, off));
        m2 = fmaxf(m2, __shfl_xor_sync(0xffffffffu, m2, off));
        m3 = fmaxf(m3, __shfl_xor_sync(0xffffffffu, m3, off));
    }

    // pass 2: exp in registers (valid chunks only), accumulate sums
    float s0 = 0.f, s1 = 0.f, s2 = 0.f, s3 = 0.f;
#pragma unroll
    for (int ch = 0; ch < 4; ch++) {
        if (ch * 32 >= degE) break;
        sc[ch].x = __expf(sc[ch].x - m0); sc[ch].y = __expf(sc[ch].y - m1);
        sc[ch].z = __expf(sc[ch].z - m2); sc[ch].w = __expf(sc[ch].w - m3);
        int k = ch * 32 + lane;
        if (k >= degE) sc[ch] = make_float4(0.f, 0.f, 0.f, 0.f);
        s0 += sc[ch].x; s1 += sc[ch].y; s2 += sc[ch].z; s3 += sc[ch].w;
    }
    if (deg > W) {  // insurance
        int n = min(g_novf, NOVF);
        for (int t = lane; t < n; t += 32) {
            if (g_ovf_r[t] == i) {
                float4 q = g_qagg[g_ovf_c[t]];
                s0 += __expf(kc.x * q.x - m0); s1 += __expf(kc.y * q.y - m1);
                s2 += __expf(kc.z * q.z - m2); s3 += __expf(kc.w * q.w - m3);
            }
        }
    }
#pragma unroll
    for (int off = 16; off; off >>= 1) {
        s0 += __shfl_xor_sync(0xffffffffu, s0, off);
        s1 += __shfl_xor_sync(0xffffffffu, s1, off);
        s2 += __shfl_xor_sync(0xffffffffu, s2, off);
        s3 += __shfl_xor_sync(0xffffffffu, s3, off);
    }
    float i0 = 0.25f / (s0 + 1e-8f);
    float i1 = 0.25f / (s1 + 1e-8f);
    float i2 = 0.25f / (s2 + 1e-8f);
    float i3 = 0.25f / (s3 + 1e-8f);

    // pass 3: weighted aggregation of fp16 h_proj[col], batched 8 edges
    // for MLP (loads issued back-to-back before consumption).
    float4 acc = make_float4(0.f, 0.f, 0.f, 0.f);
#pragma unroll
    for (int ch = 0; ch < 4; ch++) {
        int base0 = ch * 32;
        if (base0 >= degE) break;
        float w = sc[ch].x * i0 + sc[ch].y * i1 + sc[ch].z * i2 + sc[ch].w * i3;
        int rem = min(32, degE - base0);
        for (int sub = 0; sub < 4 && sub * 8 < rem; sub++) {
            int cnt = min(8, rem - sub * 8);
            int ccs[8]; float ws8[8]; uint2 hv[8];
#pragma unroll
            for (int t = 0; t < 8; t++) {
                ccs[t] = __shfl_sync(0xffffffffu, col[ch], sub * 8 + t);
                ws8[t] = __shfl_sync(0xffffffffu, w, sub * 8 + t);
            }
#pragma unroll
            for (int t = 0; t < 8; t++)
                if (t < cnt) hv[t] = ((const uint2*)g_hproj)[ccs[t] * 32 + lane];
#pragma unroll
            for (int t = 0; t < 8; t++) {
                if (t < cnt) {
                    float2 f01 = __half22float2(*(__half2*)&hv[t].x);
                    float2 f23 = __half22float2(*(__half2*)&hv[t].y);
                    acc.x = fmaf(ws8[t], f01.x, acc.x);
                    acc.y = fmaf(ws8[t], f01.y, acc.y);
                    acc.z = fmaf(ws8[t], f23.x, acc.z);
                    acc.w = fmaf(ws8[t], f23.y, acc.w);
                }
            }
        }
    }
    if (deg > W) {  // insurance: scalar broadcast over overflow list
        int n = min(g_novf, NOVF);
        for (int t = 0; t < n; t++) {
            int rr = g_ovf_r[t];
            if (rr == i) {
                int cc = g_ovf_c[t];
                float4 q = g_qagg[cc];
                float ww = __expf(kc.x * q.x - m0) * i0 + __expf(kc.y * q.y - m1) * i1 +
                           __expf(kc.z * q.z - m2) * i2 + __expf(kc.w * q.w - m3) * i3;
                uint2 hv = ((const uint2*)g_hproj)[cc * 32 + lane];
                float2 f01 = __half22float2(*(__half2*)&hv.x);
                float2 f23 = __half22float2(*(__half2*)&hv.y);
                acc.x = fmaf(ww, f01.x, acc.x);
                acc.y = fmaf(ww, f01.y, acc.y);
                acc.z = fmaf(ww, f23.x, acc.z);
                acc.w = fmaf(ww, f23.y, acc.w);
            }
        }
    }
    float4 o;
    o.x = acc.x >= 0.f ? acc.x : NEG * acc.x;
    o.y = acc.y >= 0.f ? acc.y : NEG * acc.y;
    o.z = acc.z >= 0.f ? acc.z : NEG * acc.z;
    o.w = acc.w >= 0.f ? acc.w : NEG * acc.w;
    ((float4*)out)[i * 32 + lane] = o;
}

// ---------------- launch ----------------
extern "C" void kernel_launch(void* const* d_in, const int* in_sizes, int n_in,
                              void* d_out, int out_size) {
    const float* x  = (const float*)d_in[0];
    const int*   ei = (const int*)d_in[1];
    const float* Wq = (const float*)d_in[2];
    const float* Wk = (const float*)d_in[3];
    const float* Wl = (const float*)d_in[4];
    const float* bl = (const float*)d_in[5];
    float* out = (float*)d_out;

    kzero<<<(NN + 255) / 256, 256>>>();
    kbuild<<<(NE / 4 + 255) / 256, 256>>>(ei);
    kprojsmall<<<(NN * 32 + 255) / 256, 256>>>(x, Wq, Wk);
    kgemm<<<(NN + 127) / 128, 256>>>(x, Wl, bl);
    kqagg<<<(NN * 32 + 511) / 512, 512>>>();
    kmain<<<(NN * 32 + 255) / 256, 256>>>(out);
}

// round 10
// speedup vs baseline: 1.2868x; 1.0646x over previous
#include <cuda_runtime.h>
#include <cuda_fp16.h>

#define NN 50000
#define NE 1600000
#define NEG 0.2f
#define W 128           // ELL width (in-degree is Poisson(32); max ~65)
#define NOVF 65536      // overflow insurance capacity

// ---------------- scratch (device globals; no allocation allowed) ----------
__device__ float4 g_hq[NN];          // per-node h_q (4 heads)
__device__ float4 g_kact[NN];        // per-node leaky(x@Wk^T)
__device__ float4 g_qagg[NN];        // per-node aggregated q
__device__ __half g_hproj[NN * 128]; // per-node x@Wl^T + bl (fp16 storage)
__device__ int    g_deg[NN];
__device__ int    g_ell[NN * W];     // ELL adjacency: cols of incoming edges
__device__ int    g_ovf_r[NOVF];
__device__ int    g_ovf_c[NOVF];
__device__ int    g_novf;

// ---------------- init ----------------
__global__ void kzero() {
    int i = blockIdx.x * blockDim.x + threadIdx.x;
    if (i < NN) g_deg[i] = 0;
    if (i == 0) g_novf = 0;
}

// ---------------- single-pass ELL build, 4 edges/thread for MLP ------------
__global__ void kbuild(const int* __restrict__ ei) {
    int t = blockIdx.x * blockDim.x + threadIdx.x;
    int e0 = t * 4;
    if (e0 >= NE) return;
    int4 r4 = *(const int4*)&ei[e0];
    int4 c4 = *(const int4*)&ei[NE + e0];
    int rr[4] = {r4.x, r4.y, r4.z, r4.w};
    int cc[4] = {c4.x, c4.y, c4.z, c4.w};
    int pp[4];
#pragma unroll
    for (int j = 0; j < 4; j++) pp[j] = atomicAdd(&g_deg[rr[j]], 1);
#pragma unroll
    for (int j = 0; j < 4; j++) {
        if (pp[j] < W) {
            g_ell[rr[j] * W + pp[j]] = cc[j];
        } else {
            int o = atomicAdd(&g_novf, 1);
            if (o < NOVF) { g_ovf_r[o] = rr[j]; g_ovf_c[o] = cc[j]; }
        }
    }
}

// ---------------- per-node small projections: h_q, k_act -------------------
__global__ void kprojsmall(const float* __restrict__ x,
                           const float* __restrict__ Wq,
                           const float* __restrict__ Wk) {
    int w = (blockIdx.x * blockDim.x + threadIdx.x) >> 5;
    int lane = threadIdx.x & 31;
    if (w >= NN) return;
    float4 xv = ((const float4*)x)[w * 32 + lane];
    float a[8];
#pragma unroll
    for (int h = 0; h < 4; h++) {
        float4 q = ((const float4*)Wq)[h * 32 + lane];
        float4 k = ((const float4*)Wk)[h * 32 + lane];
        a[h]     = xv.x * q.x + xv.y * q.y + xv.z * q.z + xv.w * q.w;
        a[4 + h] = xv.x * k.x + xv.y * k.y + xv.z * k.z + xv.w * k.w;
    }
#pragma unroll
    for (int off = 16; off; off >>= 1) {
#pragma unroll
        for (int h = 0; h < 8; h++) a[h] += __shfl_xor_sync(0xffffffffu, a[h], off);
    }
    if (lane == 0) {
        g_hq[w] = make_float4(a[0], a[1], a[2], a[3]);
        float4 kk;
        kk.x = a[4] >= 0.f ? a[4] : NEG * a[4];
        kk.y = a[5] >= 0.f ? a[5] : NEG * a[5];
        kk.z = a[6] >= 0.f ? a[6] : NEG * a[6];
        kk.w = a[7] >= 0.f ? a[7] : NEG * a[7];
        g_kact[w] = kk;
    }
}

// ---------------- h_proj GEMM via HMMA (fp16 in, fp32 acc, fp16 store) -----
#define XS_STRIDE 72
__global__ __launch_bounds__(256) void kgemm(const float* __restrict__ x,
                                             const float* __restrict__ Wl,
                                             const float* __restrict__ bl) {
    __shared__ __half xs[128 * XS_STRIDE];
    __shared__ __half ws[128 * XS_STRIDE];
    int nb = blockIdx.x * 128;
    int tid = threadIdx.x;
    int wid = tid >> 5;
    int lane = tid & 31;
    int warp_m = wid & 3;
    int warp_n = wid >> 2;
    int group = lane >> 2;        // 0..7
    int qk = (lane & 3) * 2;      // 0,2,4,6

    float acc[2][8][4];
#pragma unroll
    for (int mi = 0; mi < 2; mi++)
#pragma unroll
        for (int ni = 0; ni < 8; ni++)
#pragma unroll
            for (int r = 0; r < 4; r++) acc[mi][ni][r] = 0.f;

    for (int ko = 0; ko < 2; ko++) {          // two 64-wide K chunks
#pragma unroll
        for (int it = 0; it < 8; it++) {
            int idx = tid + it * 256;          // 0..2047
            int row = idx >> 4, c = idx & 15;
            float4 v = make_float4(0.f, 0.f, 0.f, 0.f);
            if (nb + row < NN) v = ((const float4*)x)[(nb + row) * 32 + ko * 16 + c];
            __half2 h01 = __floats2half2_rn(v.x, v.y);
            __half2 h23 = __floats2half2_rn(v.z, v.w);
            uint2 pk = make_uint2(*(unsigned*)&h01, *(unsigned*)&h23);
            *(uint2*)&xs[row * XS_STRIDE + c * 4] = pk;
            float4 wv = ((const float4*)Wl)[row * 32 + ko * 16 + c];
            __half2 w01 = __floats2half2_rn(wv.x, wv.y);
            __half2 w23 = __floats2half2_rn(wv.z, wv.w);
            uint2 wp = make_uint2(*(unsigned*)&w01, *(unsigned*)&w23);
            *(uint2*)&ws[row * XS_STRIDE + c * 4] = wp;
        }
        __syncthreads();
#pragma unroll
        for (int kc = 0; kc < 4; kc++) {      // four k16 sub-chunks
            unsigned a[2][4];
#pragma unroll
            for (int mi = 0; mi < 2; mi++) {
                int r0 = warp_m * 32 + mi * 16 + group;
                int base = r0 * XS_STRIDE + kc * 16 + qk;
                a[mi][0] = *(const unsigned*)&xs[base];
                a[mi][1] = *(const unsigned*)&xs[base + 8 * XS_STRIDE];
                a[mi][2] = *(const unsigned*)&xs[base + 8];
                a[mi][3] = *(const unsigned*)&xs[base + 8 * XS_STRIDE + 8];
            }
#pragma unroll
            for (int ni = 0; ni < 8; ni++) {
                int o = warp_n * 64 + ni * 8 + group;
                int wbase = o * XS_STRIDE + kc * 16 + qk;
                unsigned b0 = *(const unsigned*)&ws[wbase];
                unsigned b1 = *(const unsigned*)&ws[wbase + 8];
#pragma unroll
                for (int mi = 0; mi < 2; mi++) {
                    asm volatile(
                        "mma.sync.aligned.m16n8k16.row.col.f32.f16.f16.f32 "
                        "{%0,%1,%2,%3}, {%4,%5,%6,%7}, {%8,%9}, {%0,%1,%2,%3};"
                        : "+f"(acc[mi][ni][0]), "+f"(acc[mi][ni][1]),
                          "+f"(acc[mi][ni][2]), "+f"(acc[mi][ni][3])
                        : "r"(a[mi][0]), "r"(a[mi][1]), "r"(a[mi][2]), "r"(a[mi][3]),
                          "r"(b0), "r"(b1));
                }
            }
        }
        __syncthreads();
    }
    // epilogue: add bias, store fp16
#pragma unroll
    for (int ni = 0; ni < 8; ni++) {
        int o = warp_n * 64 + ni * 8 + qk;
        float b0 = __ldg(&bl[o]);
        float b1 = __ldg(&bl[o + 1]);
#pragma unroll
        for (int mi = 0; mi < 2; mi++) {
            int r = nb + warp_m * 32 + mi * 16 + group;
            if (r < NN) {
                __half2 h = __floats2half2_rn(acc[mi][ni][0] + b0, acc[mi][ni][1] + b1);
                *(__half2*)&g_hproj[r * 128 + o] = h;
            }
            if (r + 8 < NN) {
                __half2 h = __floats2half2_rn(acc[mi][ni][2] + b0, acc[mi][ni][3] + b1);
                *(__half2*)&g_hproj[(r + 8) * 128 + o] = h;
            }
        }
    }
}

// ---------------- q_agg: per-node sum of h_q over incoming edges -----------
__global__ __launch_bounds__(512) void kqagg() {
    int i = (blockIdx.x * blockDim.x + threadIdx.x) >> 5;
    int lane = threadIdx.x & 31;
    if (i >= NN) return;
    int deg = g_deg[i];
    int degE = min(deg, W);
    float4 a = make_float4(0.f, 0.f, 0.f, 0.f);
    for (int k = lane; k < degE; k += 32) {
        float4 q = g_hq[g_ell[i * W + k]];
        a.x += q.x; a.y += q.y; a.z += q.z; a.w += q.w;
    }
    if (deg > W) {  // insurance path (never taken for this input)
        int n = min(g_novf, NOVF);
        for (int t = lane; t < n; t += 32) {
            if (g_ovf_r[t] == i) {
                float4 q = g_hq[g_ovf_c[t]];
                a.x += q.x; a.y += q.y; a.z += q.z; a.w += q.w;
            }
        }
    }
#pragma unroll
    for (int off = 16; off; off >>= 1) {
        a.x += __shfl_xor_sync(0xffffffffu, a.x, off);
        a.y += __shfl_xor_sync(0xffffffffu, a.y, off);
        a.z += __shfl_xor_sync(0xffffffffu, a.z, off);
        a.w += __shfl_xor_sync(0xffffffffu, a.w, off);
    }
    if (lane == 0) g_qagg[i] = a;
}

// ---------------- fused softmax + aggregation + leaky ----------------------
__global__ __launch_bounds__(256) void kmain(float* __restrict__ out) {
    int i = (blockIdx.x * blockDim.x + threadIdx.x) >> 5;
    int lane = threadIdx.x & 31;
    if (i >= NN) return;
    int deg = g_deg[i];
    int degE = min(deg, W);
    float4 kc = g_kact[i];

    // pass 1: gather q_agg, scores into registers, segment max per head
    float4 sc[4];
    int col[4];
    float m0 = -1e30f, m1 = -1e30f, m2 = -1e30f, m3 = -1e30f;
#pragma unroll
    for (int ch = 0; ch < 4; ch++) {
        sc[ch] = make_float4(-1e30f, -1e30f, -1e30f, -1e30f);
        col[ch] = 0;
    }
#pragma unroll
    for (int ch = 0; ch < 4; ch++) {
        if (ch * 32 >= degE) break;
        int k = ch * 32 + lane;
        if (k < degE) {
            int c = __ldg(&g_ell[i * W + k]);
            col[ch] = c;
            float4 q = g_qagg[c];
            sc[ch].x = kc.x * q.x; sc[ch].y = kc.y * q.y;
            sc[ch].z = kc.z * q.z; sc[ch].w = kc.w * q.w;
        }
        m0 = fmaxf(m0, sc[ch].x); m1 = fmaxf(m1, sc[ch].y);
        m2 = fmaxf(m2, sc[ch].z); m3 = fmaxf(m3, sc[ch].w);
    }
    if (deg > W) {  // insurance
        int n = min(g_novf, NOVF);
        for (int t = lane; t < n; t += 32) {
            if (g_ovf_r[t] == i) {
                float4 q = g_qagg[g_ovf_c[t]];
                m0 = fmaxf(m0, kc.x * q.x); m1 = fmaxf(m1, kc.y * q.y);
                m2 = fmaxf(m2, kc.z * q.z); m3 = fmaxf(m3, kc.w * q.w);
            }
        }
    }
#pragma unroll
    for (int off = 16; off; off >>= 1) {
        m0 = fmaxf(m0, __shfl_xor_sync(0xffffffffu, m0, off));
        m1 = fmaxf(m1, __shfl_xor_sync(0xffffffffu, m1, off));
        m2 = fmaxf(m2, __shfl_xor_sync(0xffffffffu, m2, off));
        m3 = fmaxf(m3, __shfl_xor_sync(0xffffffffu, m3, off));
    }

    // pass 2: exp in registers (valid chunks only), accumulate sums
    float s0 = 0.f, s1 = 0.f, s2 = 0.f, s3 = 0.f;
#pragma unroll
    for (int ch = 0; ch < 4; ch++) {
        if (ch * 32 >= degE) break;
        sc[ch].x = __expf(sc[ch].x - m0); sc[ch].y = __expf(sc[ch].y - m1);
        sc[ch].z = __expf(sc[ch].z - m2); sc[ch].w = __expf(sc[ch].w - m3);
        int k = ch * 32 + lane;
        if (k >= degE) sc[ch] = make_float4(0.f, 0.f, 0.f, 0.f);
        s0 += sc[ch].x; s1 += sc[ch].y; s2 += sc[ch].z; s3 += sc[ch].w;
    }
    if (deg > W) {  // insurance
        int n = min(g_novf, NOVF);
        for (int t = lane; t < n; t += 32) {
            if (g_ovf_r[t] == i) {
                float4 q = g_qagg[g_ovf_c[t]];
                s0 += __expf(kc.x * q.x - m0); s1 += __expf(kc.y * q.y - m1);
                s2 += __expf(kc.z * q.z - m2); s3 += __expf(kc.w * q.w - m3);
            }
        }
    }
#pragma unroll
    for (int off = 16; off; off >>= 1) {
        s0 += __shfl_xor_sync(0xffffffffu, s0, off);
        s1 += __shfl_xor_sync(0xffffffffu, s1, off);
        s2 += __shfl_xor_sync(0xffffffffu, s2, off);
        s3 += __shfl_xor_sync(0xffffffffu, s3, off);
    }
    float i0 = 0.25f / (s0 + 1e-8f);
    float i1 = 0.25f / (s1 + 1e-8f);
    float i2 = 0.25f / (s2 + 1e-8f);
    float i3 = 0.25f / (s3 + 1e-8f);

    // pass 3: weighted aggregation of fp16 h_proj[col], batched 8 edges
    float4 acc = make_float4(0.f, 0.f, 0.f, 0.f);
#pragma unroll
    for (int ch = 0; ch < 4; ch++) {
        int base0 = ch * 32;
        if (base0 >= degE) break;
        float w = sc[ch].x * i0 + sc[ch].y * i1 + sc[ch].z * i2 + sc[ch].w * i3;
        int rem = min(32, degE - base0);
        for (int sub = 0; sub < 4 && sub * 8 < rem; sub++) {
            int cnt = min(8, rem - sub * 8);
            int ccs[8]; float ws8[8]; uint2 hv[8];
#pragma unroll
            for (int t = 0; t < 8; t++) {
                ccs[t] = __shfl_sync(0xffffffffu, col[ch], sub * 8 + t);
                ws8[t] = __shfl_sync(0xffffffffu, w, sub * 8 + t);
            }
#pragma unroll
            for (int t = 0; t < 8; t++)
                if (t < cnt) hv[t] = ((const uint2*)g_hproj)[ccs[t] * 32 + lane];
#pragma unroll
            for (int t = 0; t < 8; t++) {
                if (t < cnt) {
                    float2 f01 = __half22float2(*(__half2*)&hv[t].x);
                    float2 f23 = __half22float2(*(__half2*)&hv[t].y);
                    acc.x = fmaf(ws8[t], f01.x, acc.x);
                    acc.y = fmaf(ws8[t], f01.y, acc.y);
                    acc.z = fmaf(ws8[t], f23.x, acc.z);
                    acc.w = fmaf(ws8[t], f23.y, acc.w);
                }
            }
        }
    }
    if (deg > W) {  // insurance: scalar broadcast over overflow list
        int n = min(g_novf, NOVF);
        for (int t = 0; t < n; t++) {
            int rr = g_ovf_r[t];
            if (rr == i) {
                int cc = g_ovf_c[t];
                float4 q = g_qagg[cc];
                float ww = __expf(kc.x * q.x - m0) * i0 + __expf(kc.y * q.y - m1) * i1 +
                           __expf(kc.z * q.z - m2) * i2 + __expf(kc.w * q.w - m3) * i3;
                uint2 hv = ((const uint2*)g_hproj)[cc * 32 + lane];
                float2 f01 = __half22float2(*(__half2*)&hv.x);
                float2 f23 = __half22float2(*(__half2*)&hv.y);
                acc.x = fmaf(ww, f01.x, acc.x);
                acc.y = fmaf(ww, f01.y, acc.y);
                acc.z = fmaf(ww, f23.x, acc.z);
                acc.w = fmaf(ww, f23.y, acc.w);
            }
        }
    }
    float4 o;
    o.x = acc.x >= 0.f ? acc.x : NEG * acc.x;
    o.y = acc.y >= 0.f ? acc.y : NEG * acc.y;
    o.z = acc.z >= 0.f ? acc.z : NEG * acc.z;
    o.w = acc.w >= 0.f ? acc.w : NEG * acc.w;
    ((float4*)out)[i * 32 + lane] = o;
}

// ---------------- launch: fork independent chains onto a side stream -------
extern "C" void kernel_launch(void* const* d_in, const int* in_sizes, int n_in,
                              void* d_out, int out_size) {
    const float* x  = (const float*)d_in[0];
    const int*   ei = (const int*)d_in[1];
    const float* Wq = (const float*)d_in[2];
    const float* Wk = (const float*)d_in[3];
    const float* Wl = (const float*)d_in[4];
    const float* bl = (const float*)d_in[5];
    float* out = (float*)d_out;

    // Side stream + events (created per call; not destroyed while the main
    // stream may be in capture — bounded to the few non-replay invocations).
    cudaStream_t s1;
    cudaStreamCreateWithFlags(&s1, cudaStreamNonBlocking);
    cudaEvent_t e_fork, e_pr, e_gm;
    cudaEventCreateWithFlags(&e_fork, cudaEventDisableTiming);
    cudaEventCreateWithFlags(&e_pr, cudaEventDisableTiming);
    cudaEventCreateWithFlags(&e_gm, cudaEventDisableTiming);

    // fork: s1 depends on stream-0 head
    cudaEventRecord(e_fork, 0);
    cudaStreamWaitEvent(s1, e_fork, 0);

    // branch B (independent of edge list): small projections, then GEMM
    kprojsmall<<<(NN * 32 + 255) / 256, 256, 0, s1>>>(x, Wq, Wk);
    cudaEventRecord(e_pr, s1);
    kgemm<<<(NN + 127) / 128, 256, 0, s1>>>(x, Wl, bl);
    cudaEventRecord(e_gm, s1);

    // branch A (main stream): ELL build
    kzero<<<(NN + 255) / 256, 256>>>();
    kbuild<<<(NE / 4 + 255) / 256, 256>>>(ei);

    // join: kqagg needs kbuild (A) + kprojsmall (B)
    cudaStreamWaitEvent(0, e_pr, 0);
    kqagg<<<(NN * 32 + 511) / 512, 512>>>();

    // join: kmain additionally needs kgemm (B)
    cudaStreamWaitEvent(0, e_gm, 0);
    kmain<<<(NN * 32 + 255) / 256, 256>>>(out);
}

// round 11
// speedup vs baseline: 1.3037x; 1.0131x over previous
#include <cuda_runtime.h>
#include <cuda_fp16.h>

#define NN 50000
#define NE 1600000
#define NEG 0.2f
#define W 128           // ELL width (in-degree is Poisson(32); max ~65)
#define NOVF 65536      // overflow insurance capacity

// ---------------- scratch (device globals; no allocation allowed) ----------
__device__ float4 g_hq[NN];          // per-node h_q (4 heads)
__device__ float4 g_kact[NN];        // per-node leaky(x@Wk^T)
__device__ float4 g_qagg[NN];        // per-node aggregated q
__device__ __half g_hproj[NN * 128]; // per-node x@Wl^T + bl (fp16 storage)
__device__ int    g_deg[NN];
__device__ int    g_ell[NN * W];     // ELL adjacency: cols of incoming edges
__device__ int    g_ovf_r[NOVF];
__device__ int    g_ovf_c[NOVF];
__device__ int    g_novf;

// ---------------- init ----------------
__global__ void kzero() {
    int i = blockIdx.x * blockDim.x + threadIdx.x;
    if (i < NN) g_deg[i] = 0;
    if (i == 0) g_novf = 0;
}

// ---------------- single-pass ELL build, 8 edges/thread for MLP ------------
__global__ void kbuild(const int* __restrict__ ei) {
    int t = blockIdx.x * blockDim.x + threadIdx.x;
    int e0 = t * 8;
    if (e0 >= NE) return;
    int4 ra = *(const int4*)&ei[e0];
    int4 rb = *(const int4*)&ei[e0 + 4];
    int4 ca = *(const int4*)&ei[NE + e0];
    int4 cb = *(const int4*)&ei[NE + e0 + 4];
    int rr[8] = {ra.x, ra.y, ra.z, ra.w, rb.x, rb.y, rb.z, rb.w};
    int cc[8] = {ca.x, ca.y, ca.z, ca.w, cb.x, cb.y, cb.z, cb.w};
    int pp[8];
#pragma unroll
    for (int j = 0; j < 8; j++) pp[j] = atomicAdd(&g_deg[rr[j]], 1);
#pragma unroll
    for (int j = 0; j < 8; j++) {
        if (pp[j] < W) {
            g_ell[rr[j] * W + pp[j]] = cc[j];
        } else {
            int o = atomicAdd(&g_novf, 1);
            if (o < NOVF) { g_ovf_r[o] = rr[j]; g_ovf_c[o] = cc[j]; }
        }
    }
}

// ---------------- per-node small projections: h_q, k_act -------------------
__global__ void kprojsmall(const float* __restrict__ x,
                           const float* __restrict__ Wq,
                           const float* __restrict__ Wk) {
    int w = (blockIdx.x * blockDim.x + threadIdx.x) >> 5;
    int lane = threadIdx.x & 31;
    if (w >= NN) return;
    float4 xv = ((const float4*)x)[w * 32 + lane];
    float a[8];
#pragma unroll
    for (int h = 0; h < 4; h++) {
        float4 q = ((const float4*)Wq)[h * 32 + lane];
        float4 k = ((const float4*)Wk)[h * 32 + lane];
        a[h]     = xv.x * q.x + xv.y * q.y + xv.z * q.z + xv.w * q.w;
        a[4 + h] = xv.x * k.x + xv.y * k.y + xv.z * k.z + xv.w * k.w;
    }
#pragma unroll
    for (int off = 16; off; off >>= 1) {
#pragma unroll
        for (int h = 0; h < 8; h++) a[h] += __shfl_xor_sync(0xffffffffu, a[h], off);
    }
    if (lane == 0) {
        g_hq[w] = make_float4(a[0], a[1], a[2], a[3]);
        float4 kk;
        kk.x = a[4] >= 0.f ? a[4] : NEG * a[4];
        kk.y = a[5] >= 0.f ? a[5] : NEG * a[5];
        kk.z = a[6] >= 0.f ? a[6] : NEG * a[6];
        kk.w = a[7] >= 0.f ? a[7] : NEG * a[7];
        g_kact[w] = kk;
    }
}

// ---------------- h_proj GEMM via HMMA (fp16 in, fp32 acc, fp16 store) -----
#define XS_STRIDE 72
__global__ __launch_bounds__(256) void kgemm(const float* __restrict__ x,
                                             const float* __restrict__ Wl,
                                             const float* __restrict__ bl) {
    __shared__ __half xs[128 * XS_STRIDE];
    __shared__ __half ws[128 * XS_STRIDE];
    int nb = blockIdx.x * 128;
    int tid = threadIdx.x;
    int wid = tid >> 5;
    int lane = tid & 31;
    int warp_m = wid & 3;
    int warp_n = wid >> 2;
    int group = lane >> 2;        // 0..7
    int qk = (lane & 3) * 2;      // 0,2,4,6

    float acc[2][8][4];
#pragma unroll
    for (int mi = 0; mi < 2; mi++)
#pragma unroll
        for (int ni = 0; ni < 8; ni++)
#pragma unroll
            for (int r = 0; r < 4; r++) acc[mi][ni][r] = 0.f;

    for (int ko = 0; ko < 2; ko++) {          // two 64-wide K chunks
#pragma unroll
        for (int it = 0; it < 8; it++) {
            int idx = tid + it * 256;          // 0..2047
            int row = idx >> 4, c = idx & 15;
            float4 v = make_float4(0.f, 0.f, 0.f, 0.f);
            if (nb + row < NN) v = ((const float4*)x)[(nb + row) * 32 + ko * 16 + c];
            __half2 h01 = __floats2half2_rn(v.x, v.y);
            __half2 h23 = __floats2half2_rn(v.z, v.w);
            uint2 pk = make_uint2(*(unsigned*)&h01, *(unsigned*)&h23);
            *(uint2*)&xs[row * XS_STRIDE + c * 4] = pk;
            float4 wv = ((const float4*)Wl)[row * 32 + ko * 16 + c];
            __half2 w01 = __floats2half2_rn(wv.x, wv.y);
            __half2 w23 = __floats2half2_rn(wv.z, wv.w);
            uint2 wp = make_uint2(*(unsigned*)&w01, *(unsigned*)&w23);
            *(uint2*)&ws[row * XS_STRIDE + c * 4] = wp;
        }
        __syncthreads();
#pragma unroll
        for (int kc = 0; kc < 4; kc++) {      // four k16 sub-chunks
            unsigned a[2][4];
#pragma unroll
            for (int mi = 0; mi < 2; mi++) {
                int r0 = warp_m * 32 + mi * 16 + group;
                int base = r0 * XS_STRIDE + kc * 16 + qk;
                a[mi][0] = *(const unsigned*)&xs[base];
                a[mi][1] = *(const unsigned*)&xs[base + 8 * XS_STRIDE];
                a[mi][2] = *(const unsigned*)&xs[base + 8];
                a[mi][3] = *(const unsigned*)&xs[base + 8 * XS_STRIDE + 8];
            }
#pragma unroll
            for (int ni = 0; ni < 8; ni++) {
                int o = warp_n * 64 + ni * 8 + group;
                int wbase = o * XS_STRIDE + kc * 16 + qk;
                unsigned b0 = *(const unsigned*)&ws[wbase];
                unsigned b1 = *(const unsigned*)&ws[wbase + 8];
#pragma unroll
                for (int mi = 0; mi < 2; mi++) {
                    asm volatile(
                        "mma.sync.aligned.m16n8k16.row.col.f32.f16.f16.f32 "
                        "{%0,%1,%2,%3}, {%4,%5,%6,%7}, {%8,%9}, {%0,%1,%2,%3};"
                        : "+f"(acc[mi][ni][0]), "+f"(acc[mi][ni][1]),
                          "+f"(acc[mi][ni][2]), "+f"(acc[mi][ni][3])
                        : "r"(a[mi][0]), "r"(a[mi][1]), "r"(a[mi][2]), "r"(a[mi][3]),
                          "r"(b0), "r"(b1));
                }
            }
        }
        __syncthreads();
    }
    // epilogue: add bias, store fp16
#pragma unroll
    for (int ni = 0; ni < 8; ni++) {
        int o = warp_n * 64 + ni * 8 + qk;
        float b0 = __ldg(&bl[o]);
        float b1 = __ldg(&bl[o + 1]);
#pragma unroll
        for (int mi = 0; mi < 2; mi++) {
            int r = nb + warp_m * 32 + mi * 16 + group;
            if (r < NN) {
                __half2 h = __floats2half2_rn(acc[mi][ni][0] + b0, acc[mi][ni][1] + b1);
                *(__half2*)&g_hproj[r * 128 + o] = h;
            }
            if (r + 8 < NN) {
                __half2 h = __floats2half2_rn(acc[mi][ni][2] + b0, acc[mi][ni][3] + b1);
                *(__half2*)&g_hproj[(r + 8) * 128 + o] = h;
            }
        }
    }
}

// ---------------- q_agg: per-node sum of h_q over incoming edges -----------
__global__ __launch_bounds__(512) void kqagg() {
    int i = (blockIdx.x * blockDim.x + threadIdx.x) >> 5;
    int lane = threadIdx.x & 31;
    if (i >= NN) return;
    int deg = g_deg[i];
    int degE = min(deg, W);
    float4 a = make_float4(0.f, 0.f, 0.f, 0.f);
    for (int k = lane; k < degE; k += 32) {
        float4 q = g_hq[g_ell[i * W + k]];
        a.x += q.x; a.y += q.y; a.z += q.z; a.w += q.w;
    }
    if (deg > W) {  // insurance path (never taken for this input)
        int n = min(g_novf, NOVF);
        for (int t = lane; t < n; t += 32) {
            if (g_ovf_r[t] == i) {
                float4 q = g_hq[g_ovf_c[t]];
                a.x += q.x; a.y += q.y; a.z += q.z; a.w += q.w;
            }
        }
    }
#pragma unroll
    for (int off = 16; off; off >>= 1) {
        a.x += __shfl_xor_sync(0xffffffffu, a.x, off);
        a.y += __shfl_xor_sync(0xffffffffu, a.y, off);
        a.z += __shfl_xor_sync(0xffffffffu, a.z, off);
        a.w += __shfl_xor_sync(0xffffffffu, a.w, off);
    }
    if (lane == 0) g_qagg[i] = a;
}

// ---------------- fused softmax + aggregation + leaky ----------------------
__global__ __launch_bounds__(256) void kmain(float* __restrict__ out) {
    int i = (blockIdx.x * blockDim.x + threadIdx.x) >> 5;
    int lane = threadIdx.x & 31;
    if (i >= NN) return;
    int deg = g_deg[i];
    int degE = min(deg, W);
    float4 kc = g_kact[i];

    // pass 1: gather q_agg, scores into registers, segment max per head
    float4 sc[4];
    int col[4];
    float m0 = -1e30f, m1 = -1e30f, m2 = -1e30f, m3 = -1e30f;
#pragma unroll
    for (int ch = 0; ch < 4; ch++) {
        sc[ch] = make_float4(-1e30f, -1e30f, -1e30f, -1e30f);
        col[ch] = 0;
    }
#pragma unroll
    for (int ch = 0; ch < 4; ch++) {
        if (ch * 32 >= degE) break;
        int k = ch * 32 + lane;
        if (k < degE) {
            int c = __ldg(&g_ell[i * W + k]);
            col[ch] = c;
            float4 q = g_qagg[c];
            sc[ch].x = kc.x * q.x; sc[ch].y = kc.y * q.y;
            sc[ch].z = kc.z * q.z; sc[ch].w = kc.w * q.w;
        }
        m0 = fmaxf(m0, sc[ch].x); m1 = fmaxf(m1, sc[ch].y);
        m2 = fmaxf(m2, sc[ch].z); m3 = fmaxf(m3, sc[ch].w);
    }
    if (deg > W) {  // insurance
        int n = min(g_novf, NOVF);
        for (int t = lane; t < n; t += 32) {
            if (g_ovf_r[t] == i) {
                float4 q = g_qagg[g_ovf_c[t]];
                m0 = fmaxf(m0, kc.x * q.x); m1 = fmaxf(m1, kc.y * q.y);
                m2 = fmaxf(m2, kc.z * q.z); m3 = fmaxf(m3, kc.w * q.w);
            }
        }
    }
#pragma unroll
    for (int off = 16; off; off >>= 1) {
        m0 = fmaxf(m0, __shfl_xor_sync(0xffffffffu, m0, off));
        m1 = fmaxf(m1, __shfl_xor_sync(0xffffffffu, m1, off));
        m2 = fmaxf(m2, __shfl_xor_sync(0xffffffffu, m2, off));
        m3 = fmaxf(m3, __shfl_xor_sync(0xffffffffu, m3, off));
    }

    // pass 2: exp via ex2.approx.f16x2 (2 values per MUFU op). Args are
    // max-subtracted (<= 0) so results are in [0,1]: no fp16 overflow, and
    // large-negative args underflow to 0 (correct for softmax). Invalid
    // lanes (-1e30) convert to -inf -> ex2 -> 0.
    float s0 = 0.f, s1 = 0.f, s2 = 0.f, s3 = 0.f;
#pragma unroll
    for (int ch = 0; ch < 4; ch++) {
        if (ch * 32 >= degE) break;
        const float L2E = 1.442695041f;
        __half2 ha = __floats2half2_rn((sc[ch].x - m0) * L2E, (sc[ch].y - m1) * L2E);
        __half2 hb = __floats2half2_rn((sc[ch].z - m2) * L2E, (sc[ch].w - m3) * L2E);
        unsigned ua = *(unsigned*)&ha, ub = *(unsigned*)&hb;
        unsigned ra, rb;
        asm("ex2.approx.f16x2 %0, %1;" : "=r"(ra) : "r"(ua));
        asm("ex2.approx.f16x2 %0, %1;" : "=r"(rb) : "r"(ub));
        float2 ea = __half22float2(*(__half2*)&ra);
        float2 eb = __half22float2(*(__half2*)&rb);
        sc[ch].x = ea.x; sc[ch].y = ea.y; sc[ch].z = eb.x; sc[ch].w = eb.y;
        int k = ch * 32 + lane;
        if (k >= degE) sc[ch] = make_float4(0.f, 0.f, 0.f, 0.f);
        s0 += sc[ch].x; s1 += sc[ch].y; s2 += sc[ch].z; s3 += sc[ch].w;
    }
    if (deg > W) {  // insurance
        int n = min(g_novf, NOVF);
        for (int t = lane; t < n; t += 32) {
            if (g_ovf_r[t] == i) {
                float4 q = g_qagg[g_ovf_c[t]];
                s0 += __expf(kc.x * q.x - m0); s1 += __expf(kc.y * q.y - m1);
                s2 += __expf(kc.z * q.z - m2); s3 += __expf(kc.w * q.w - m3);
            }
        }
    }
#pragma unroll
    for (int off = 16; off; off >>= 1) {
        s0 += __shfl_xor_sync(0xffffffffu, s0, off);
        s1 += __shfl_xor_sync(0xffffffffu, s1, off);
        s2 += __shfl_xor_sync(0xffffffffu, s2, off);
        s3 += __shfl_xor_sync(0xffffffffu, s3, off);
    }
    float i0 = 0.25f / (s0 + 1e-8f);
    float i1 = 0.25f / (s1 + 1e-8f);
    float i2 = 0.25f / (s2 + 1e-8f);
    float i3 = 0.25f / (s3 + 1e-8f);

    // pass 3: weighted aggregation of fp16 h_proj[col], batched 8 edges
    float4 acc = make_float4(0.f, 0.f, 0.f, 0.f);
#pragma unroll
    for (int ch = 0; ch < 4; ch++) {
        int base0 = ch * 32;
        if (base0 >= degE) break;
        float w = sc[ch].x * i0 + sc[ch].y * i1 + sc[ch].z * i2 + sc[ch].w * i3;
        int rem = min(32, degE - base0);
        for (int sub = 0; sub < 4 && sub * 8 < rem; sub++) {
            int cnt = min(8, rem - sub * 8);
            int ccs[8]; float ws8[8]; uint2 hv[8];
#pragma unroll
            for (int t = 0; t < 8; t++) {
                ccs[t] = __shfl_sync(0xffffffffu, col[ch], sub * 8 + t);
                ws8[t] = __shfl_sync(0xffffffffu, w, sub * 8 + t);
            }
#pragma unroll
            for (int t = 0; t < 8; t++)
                if (t < cnt) hv[t] = ((const uint2*)g_hproj)[ccs[t] * 32 + lane];
#pragma unroll
            for (int t = 0; t < 8; t++) {
                if (t < cnt) {
                    float2 f01 = __half22float2(*(__half2*)&hv[t].x);
                    float2 f23 = __half22float2(*(__half2*)&hv[t].y);
                    acc.x = fmaf(ws8[t], f01.x, acc.x);
                    acc.y = fmaf(ws8[t], f01.y, acc.y);
                    acc.z = fmaf(ws8[t], f23.x, acc.z);
                    acc.w = fmaf(ws8[t], f23.y, acc.w);
                }
            }
        }
    }
    if (deg > W) {  // insurance: scalar broadcast over overflow list
        int n = min(g_novf, NOVF);
        for (int t = 0; t < n; t++) {
            int rr = g_ovf_r[t];
            if (rr == i) {
                int cc = g_ovf_c[t];
                float4 q = g_qagg[cc];
                float ww = __expf(kc.x * q.x - m0) * i0 + __expf(kc.y * q.y - m1) * i1 +
                           __expf(kc.z * q.z - m2) * i2 + __expf(kc.w * q.w - m3) * i3;
                uint2 hv = ((const uint2*)g_hproj)[cc * 32 + lane];
                float2 f01 = __half22float2(*(__half2*)&hv.x);
                float2 f23 = __half22float2(*(__half2*)&hv.y);
                acc.x = fmaf(ww, f01.x, acc.x);
                acc.y = fmaf(ww, f01.y, acc.y);
                acc.z = fmaf(ww, f23.x, acc.z);
                acc.w = fmaf(ww, f23.y, acc.w);
            }
        }
    }
    float4 o;
    o.x = acc.x >= 0.f ? acc.x : NEG * acc.x;
    o.y = acc.y >= 0.f ? acc.y : NEG * acc.y;
    o.z = acc.z >= 0.f ? acc.z : NEG * acc.z;
    o.w = acc.w >= 0.f ? acc.w : NEG * acc.w;
    ((float4*)out)[i * 32 + lane] = o;
}

// ---------------- launch: fork independent chains onto a side stream -------
extern "C" void kernel_launch(void* const* d_in, const int* in_sizes, int n_in,
                              void* d_out, int out_size) {
    const float* x  = (const float*)d_in[0];
    const int*   ei = (const int*)d_in[1];
    const float* Wq = (const float*)d_in[2];
    const float* Wk = (const float*)d_in[3];
    const float* Wl = (const float*)d_in[4];
    const float* bl = (const float*)d_in[5];
    float* out = (float*)d_out;

    cudaStream_t s1;
    cudaStreamCreateWithFlags(&s1, cudaStreamNonBlocking);
    cudaEvent_t e_fork, e_pr, e_gm;
    cudaEventCreateWithFlags(&e_fork, cudaEventDisableTiming);
    cudaEventCreateWithFlags(&e_pr, cudaEventDisableTiming);
    cudaEventCreateWithFlags(&e_gm, cudaEventDisableTiming);

    // fork: s1 depends on stream-0 head
    cudaEventRecord(e_fork, 0);
    cudaStreamWaitEvent(s1, e_fork, 0);

    // branch B (independent of edge list): small projections, then GEMM
    kprojsmall<<<(NN * 32 + 255) / 256, 256, 0, s1>>>(x, Wq, Wk);
    cudaEventRecord(e_pr, s1);
    kgemm<<<(NN + 127) / 128, 256, 0, s1>>>(x, Wl, bl);
    cudaEventRecord(e_gm, s1);

    // branch A (main stream): ELL build
    kzero<<<(NN + 255) / 256, 256>>>();
    kbuild<<<(NE / 8 + 255) / 256, 256>>>(ei);

    // join: kqagg needs kbuild (A) + kprojsmall (B)
    cudaStreamWaitEvent(0, e_pr, 0);
    kqagg<<<(NN * 32 + 511) / 512, 512>>>();

    // join: kmain additionally needs kgemm (B)
    cudaStreamWaitEvent(0, e_gm, 0);
    kmain<<<(NN * 32 + 255) / 256, 256>>>(out);
}